// round 1
// baseline (speedup 1.0000x reference)
#include <cuda_runtime.h>
#include <math.h>

#define B_ 4
#define N_ 4096
#define D_ 1024
#define E_ 8
#define M_ 512   // N/E tokens per expert

// ---------------- scratch (device globals; no allocation allowed) ----------------
__device__ float g_t[B_ * N_ * E_];         // gate logits -> log-gates; after sinkhorn: [b][e][n] layout
__device__ int   g_topk_idx[B_ * E_ * M_];  // sorted token indices per (b,e), descending gate
__device__ float g_topk_val[B_ * E_ * M_];  // matching gate values
__device__ int   g_winner[B_ * N_];         // per-token winning key m*E+e (last-wins), -1 if unrouted

// ---------------- 1) gate logits + log(clamp(.,1e-6)) ----------------
__global__ void gate_logits_kernel(const float* __restrict__ x, const float* __restrict__ gw) {
    __shared__ float sw[E_ * D_];  // transposed: [e][d]
    for (int i = threadIdx.x; i < D_ * E_; i += blockDim.x) {
        int d = i / E_, e = i % E_;
        sw[e * D_ + d] = gw[i];
    }
    __syncthreads();
    int warp = threadIdx.x >> 5, lane = threadIdx.x & 31;
    int row = blockIdx.x * (blockDim.x >> 5) + warp;   // global token index b*N+n
    if (row >= B_ * N_) return;
    const float* xr = x + (size_t)row * D_;
    float acc[E_];
#pragma unroll
    for (int e = 0; e < E_; e++) acc[e] = 0.f;
    for (int d = lane; d < D_; d += 32) {
        float xv = xr[d];
#pragma unroll
        for (int e = 0; e < E_; e++) acc[e] += xv * sw[e * D_ + d];
    }
#pragma unroll
    for (int e = 0; e < E_; e++) {
#pragma unroll
        for (int off = 16; off; off >>= 1)
            acc[e] += __shfl_xor_sync(0xFFFFFFFFu, acc[e], off);
    }
    if (lane == 0) {
#pragma unroll
        for (int e = 0; e < E_; e++)
            g_t[(size_t)row * E_ + e] = logf(fmaxf(acc[e], 1e-6f));
    }
}

// ---------------- 2) Sinkhorn (8 iters) per batch, entirely in smem ----------------
// dyn smem: st[E][N] = 128KB.  Writes back g_t in [b][e][n] layout.
__global__ void sinkhorn_kernel() {
    extern __shared__ float st[];                 // [E_][N_]
    __shared__ float s_m[32], s_s[32], lse_col[E_];
    int b = blockIdx.x, tid = threadIdx.x;
    for (int i = tid; i < N_ * E_; i += blockDim.x) {
        int e = i >> 12, n = i & (N_ - 1);
        st[i] = g_t[(size_t)b * N_ * E_ + (size_t)n * E_ + e];
    }
    __syncthreads();
    int warp = tid >> 5, lane = tid & 31;
    int e_w = warp & 7, seg = warp >> 3;          // warp handles expert e_w, row segment seg (1024 rows)
    for (int it = 0; it < 8; it++) {
        // ---- column LSE (over tokens), online per-lane then warp merge ----
        float m = -INFINITY, s = 0.f;
        int base = e_w * N_ + seg * 1024 + lane;
#pragma unroll 4
        for (int k = 0; k < 32; k++) {
            float v = st[base + k * 32];
            float nm = fmaxf(m, v);
            s = s * expf(m - nm) + expf(v - nm);
            m = nm;
        }
#pragma unroll
        for (int off = 16; off; off >>= 1) {
            float om = __shfl_xor_sync(0xFFFFFFFFu, m, off);
            float os = __shfl_xor_sync(0xFFFFFFFFu, s, off);
            float nm = fmaxf(m, om);
            s = s * expf(m - nm) + os * expf(om - nm);
            m = nm;
        }
        if (lane == 0) { s_m[warp] = m; s_s[warp] = s; }
        __syncthreads();
        if (tid < E_) {
            float mm = -INFINITY, ss = 0.f;
#pragma unroll
            for (int q = 0; q < 4; q++) {
                float om = s_m[q * 8 + tid], os = s_s[q * 8 + tid];
                float nm = fmaxf(mm, om);
                ss = ss * expf(mm - nm) + os * expf(om - nm);
                mm = nm;
            }
            lse_col[tid] = mm + logf(ss);
        }
        __syncthreads();
        for (int i = tid; i < N_ * E_; i += blockDim.x)
            st[i] -= lse_col[i >> 12];
        __syncthreads();
        // ---- row LSE (over experts), per-thread ----
        for (int n = tid; n < N_; n += blockDim.x) {
            float mm = -INFINITY;
#pragma unroll
            for (int e = 0; e < E_; e++) mm = fmaxf(mm, st[e * N_ + n]);
            float ss = 0.f;
#pragma unroll
            for (int e = 0; e < E_; e++) ss += expf(st[e * N_ + n] - mm);
            float l = mm + logf(ss);
#pragma unroll
            for (int e = 0; e < E_; e++) st[e * N_ + n] -= l;
        }
        __syncthreads();
    }
    for (int i = tid; i < N_ * E_; i += blockDim.x)
        g_t[(size_t)b * N_ * E_ + i] = st[i];     // [e][n] layout now
}

// ---------------- 3) full descending sort of each (b,e) column; emit top-512 ----------------
// Key: (orderable float bits of log-gate) desc, token index asc on ties — matches jax.lax.top_k.
__global__ void topk_sort_kernel() {
    __shared__ unsigned long long keys[N_];
    int b = blockIdx.x >> 3, e = blockIdx.x & 7;
    int tid = threadIdx.x;
    const float* tcol = g_t + (size_t)b * N_ * E_ + (size_t)e * N_;
    for (int i = tid; i < N_; i += blockDim.x) {
        unsigned int u = __float_as_uint(tcol[i]);
        u = (u & 0x80000000u) ? ~u : (u | 0x80000000u);   // ascending-orderable
        keys[i] = ((unsigned long long)u << 32) | (unsigned int)(N_ - 1 - i);
    }
    __syncthreads();
    for (int k = 2; k <= N_; k <<= 1) {
        for (int j = k >> 1; j > 0; j >>= 1) {
            for (int i = tid; i < N_; i += blockDim.x) {
                int l = i ^ j;
                if (l > i) {
                    unsigned long long a = keys[i], c = keys[l];
                    bool desc = ((i & k) == 0);
                    if (desc ? (a < c) : (a > c)) { keys[i] = c; keys[l] = a; }
                }
            }
            __syncthreads();
        }
    }
    for (int m = tid; m < M_; m += blockDim.x) {
        unsigned long long K = keys[m];
        int n = (N_ - 1) - (int)(unsigned int)(K & 0xFFFFFFFFull);
        int o = (b * E_ + e) * M_ + m;
        g_topk_idx[o] = n;
        g_topk_val[o] = expf(tcol[n]);
    }
}

// ---------------- 4) zero output + init winner ----------------
__global__ void zero_init_kernel(float4* __restrict__ out) {
    int i = blockIdx.x * blockDim.x + threadIdx.x;
    out[i] = make_float4(0.f, 0.f, 0.f, 0.f);
    if (i < B_ * N_) g_winner[i] = -1;
}

// ---------------- 5) duplicate resolution: last-wins over (m,e) row-major ----------------
__global__ void winner_scatter_kernel() {
    int i = blockIdx.x * blockDim.x + threadIdx.x;
    if (i >= B_ * E_ * M_) return;
    int b = i / (E_ * M_);
    int r = i - b * (E_ * M_);
    int e = r / M_;
    int m = r - e * M_;
    int n = g_topk_idx[i];
    atomicMax(&g_winner[b * N_ + n], m * E_ + e);
}

// ---------------- 6) gathered expert GEMM + scale + winner scatter ----------------
// Per (b,e): C[512,1024] = gather(x)[512,1024] @ experts[e][1024,1024]
// 64x64 tile, BK=16, 4x4 per thread, 256 threads.
__global__ __launch_bounds__(256) void expert_gemm_kernel(
    const float* __restrict__ x, const float* __restrict__ experts, float* __restrict__ out) {
    __shared__ float As[16][64];   // [k][m]
    __shared__ float Bs[16][64];   // [k][f]
    __shared__ int   s_n[64];
    __shared__ float s_v[64];
    __shared__ unsigned char s_w[64];

    int bz = blockIdx.z;  int b = bz >> 3;  int e = bz & 7;
    int m0 = blockIdx.x * 64, f0 = blockIdx.y * 64;
    int tid = threadIdx.x;

    if (tid < 64) {
        int m = m0 + tid;
        int o = bz * M_ + m;
        int n = g_topk_idx[o];
        s_n[tid] = n;
        s_v[tid] = g_topk_val[o];
        s_w[tid] = (g_winner[b * N_ + n] == m * E_ + e) ? 1 : 0;
    }
    __syncthreads();

    const float* Bp = experts + (size_t)e * D_ * D_;
    const float* xb = x + (size_t)b * N_ * D_;
    int ty = tid >> 4, tx = tid & 15;
    int ar = tid >> 2, ak = (tid & 3) << 2;   // A load: row ar (0..63), k offset ak
    int bk = tid >> 4, bf = (tid & 15) << 2;  // B load: k row bk (0..15), f offset bf

    const float* arow = xb + (size_t)s_n[ar] * D_ + ak;

    float acc[16];
#pragma unroll
    for (int i = 0; i < 16; i++) acc[i] = 0.f;

    for (int k0 = 0; k0 < D_; k0 += 16) {
        float4 av = *(const float4*)(arow + k0);
        As[ak + 0][ar] = av.x; As[ak + 1][ar] = av.y;
        As[ak + 2][ar] = av.z; As[ak + 3][ar] = av.w;
        float4 bv = *(const float4*)(Bp + (size_t)(k0 + bk) * D_ + f0 + bf);
        *(float4*)&Bs[bk][bf] = bv;
        __syncthreads();
#pragma unroll
        for (int k = 0; k < 16; k++) {
            float4 a  = *(const float4*)&As[k][ty << 2];
            float4 bb = *(const float4*)&Bs[k][tx << 2];
            acc[ 0] += a.x * bb.x; acc[ 1] += a.x * bb.y; acc[ 2] += a.x * bb.z; acc[ 3] += a.x * bb.w;
            acc[ 4] += a.y * bb.x; acc[ 5] += a.y * bb.y; acc[ 6] += a.y * bb.z; acc[ 7] += a.y * bb.w;
            acc[ 8] += a.z * bb.x; acc[ 9] += a.z * bb.y; acc[10] += a.z * bb.z; acc[11] += a.z * bb.w;
            acc[12] += a.w * bb.x; acc[13] += a.w * bb.y; acc[14] += a.w * bb.z; acc[15] += a.w * bb.w;
        }
        __syncthreads();
    }

#pragma unroll
    for (int i = 0; i < 4; i++) {
        int r = (ty << 2) + i;
        if (s_w[r]) {
            float sv = s_v[r];
            float4 o4;
            o4.x = acc[i * 4 + 0] * sv; o4.y = acc[i * 4 + 1] * sv;
            o4.z = acc[i * 4 + 2] * sv; o4.w = acc[i * 4 + 3] * sv;
            *(float4*)(out + ((size_t)b * N_ + s_n[r]) * D_ + f0 + (tx << 2)) = o4;
        }
    }
}

// ---------------- launch ----------------
extern "C" void kernel_launch(void* const* d_in, const int* in_sizes, int n_in,
                              void* d_out, int out_size) {
    const float* x       = (const float*)d_in[0];
    const float* gw      = (const float*)d_in[1];
    const float* experts = (const float*)d_in[2];
    float* out = (float*)d_out;

    cudaFuncSetAttribute(sinkhorn_kernel, cudaFuncAttributeMaxDynamicSharedMemorySize,
                         N_ * E_ * (int)sizeof(float));

    gate_logits_kernel<<<(B_ * N_) / 8, 256>>>(x, gw);
    sinkhorn_kernel<<<B_, 1024, N_ * E_ * sizeof(float)>>>();
    topk_sort_kernel<<<B_ * E_, 1024>>>();
    zero_init_kernel<<<(B_ * N_ * D_ / 4) / 256, 256>>>((float4*)out);
    winner_scatter_kernel<<<(B_ * E_ * M_ + 255) / 256, 256>>>();
    expert_gemm_kernel<<<dim3(M_ / 64, D_ / 64, B_ * E_), 256>>>(x, experts, out);
}

// round 4
// speedup vs baseline: 2.2450x; 2.2450x over previous
#include <cuda_runtime.h>
#include <cuda_bf16.h>
#include <math.h>
#include <stdint.h>

#define B_ 4
#define N_ 4096
#define D_ 1024
#define E_ 8
#define M_ 512   // N/E tokens per expert

// ---------------- scratch (device globals; no allocation allowed) ----------------
__device__ float g_t[B_ * N_ * E_];         // gate logits -> log-gates; after sinkhorn: [b][e][n] layout
__device__ int   g_topk_idx[B_ * E_ * M_];  // sorted token indices per (b,e), descending gate
__device__ float g_topk_val[B_ * E_ * M_];  // matching gate values
__device__ int   g_winner[B_ * N_];         // per-token winning key m*E+e (last-wins), -1 if unrouted

// bf16 split-precision operands for the tensor-core GEMM
__device__ __nv_bfloat16 g_xh[B_ * N_ * D_];   // hi(x)
__device__ __nv_bfloat16 g_xl[B_ * N_ * D_];   // lo(x)
__device__ __nv_bfloat16 g_wth[E_ * D_ * D_];  // hi(W^T): [e][f][k]
__device__ __nv_bfloat16 g_wtl[E_ * D_ * D_];  // lo(W^T)

__device__ __forceinline__ uint32_t smem_u32(const void* p) {
    uint32_t a;
    asm("{ .reg .u64 t; cvta.to.shared.u64 t, %1; cvt.u32.u64 %0, t; }" : "=r"(a) : "l"(p));
    return a;
}
__device__ __forceinline__ void cp16(uint32_t dst, const void* src) {
    asm volatile("cp.async.cg.shared.global [%0], [%1], 16;" :: "r"(dst), "l"(src));
}
__device__ __forceinline__ void ldsm4(uint32_t* r, uint32_t addr) {
    asm volatile("ldmatrix.sync.aligned.m8n8.x4.shared.b16 {%0,%1,%2,%3}, [%4];"
                 : "=r"(r[0]), "=r"(r[1]), "=r"(r[2]), "=r"(r[3]) : "r"(addr));
}
__device__ __forceinline__ void mma16816(float* d, const uint32_t* a, const uint32_t* b) {
    asm volatile(
        "mma.sync.aligned.m16n8k16.row.col.f32.bf16.bf16.f32 "
        "{%0,%1,%2,%3}, {%4,%5,%6,%7}, {%8,%9}, {%0,%1,%2,%3};"
        : "+f"(d[0]), "+f"(d[1]), "+f"(d[2]), "+f"(d[3])
        : "r"(a[0]), "r"(a[1]), "r"(a[2]), "r"(a[3]), "r"(b[0]), "r"(b[1]));
}

// ---------------- 0a) split x into bf16 hi/lo ----------------
__global__ void convert_x_kernel(const float4* __restrict__ x) {
    int i = blockIdx.x * blockDim.x + threadIdx.x;  // over B*N*D/4
    float4 v = x[i];
    __nv_bfloat16 hx = __float2bfloat16(v.x), hy = __float2bfloat16(v.y);
    __nv_bfloat16 hz = __float2bfloat16(v.z), hw = __float2bfloat16(v.w);
    __nv_bfloat162* ph = (__nv_bfloat162*)g_xh;
    __nv_bfloat162* pl = (__nv_bfloat162*)g_xl;
    ph[2 * i]     = __nv_bfloat162{hx, hy};
    ph[2 * i + 1] = __nv_bfloat162{hz, hw};
    pl[2 * i]     = __nv_bfloat162{__float2bfloat16(v.x - __bfloat162float(hx)),
                                   __float2bfloat16(v.y - __bfloat162float(hy))};
    pl[2 * i + 1] = __nv_bfloat162{__float2bfloat16(v.z - __bfloat162float(hz)),
                                   __float2bfloat16(v.w - __bfloat162float(hw))};
}

// ---------------- 0b) transpose experts to [e][f][k], split bf16 hi/lo ----------------
__global__ void convert_w_kernel(const float* __restrict__ w) {
    __shared__ float t[32][33];
    int e = blockIdx.z;
    int k0 = blockIdx.x * 32, f0 = blockIdx.y * 32;
    int tx = threadIdx.x, ty = threadIdx.y;  // 32 x 8
    const float* wb = w + (size_t)e * D_ * D_;
#pragma unroll
    for (int j = 0; j < 32; j += 8)
        t[ty + j][tx] = wb[(size_t)(k0 + ty + j) * D_ + f0 + tx];
    __syncthreads();
#pragma unroll
    for (int j = 0; j < 32; j += 8) {
        float v = t[tx][ty + j];
        __nv_bfloat16 h = __float2bfloat16(v);
        size_t o = (size_t)e * D_ * D_ + (size_t)(f0 + ty + j) * D_ + k0 + tx;
        g_wth[o] = h;
        g_wtl[o] = __float2bfloat16(v - __bfloat162float(h));
    }
}

// ---------------- 1) gate logits + log(clamp(.,1e-6)) ----------------
__global__ void gate_logits_kernel(const float* __restrict__ x, const float* __restrict__ gw) {
    __shared__ float sw[E_ * D_];  // transposed: [e][d]
    for (int i = threadIdx.x; i < D_ * E_; i += blockDim.x) {
        int d = i / E_, e = i % E_;
        sw[e * D_ + d] = gw[i];
    }
    __syncthreads();
    int warp = threadIdx.x >> 5, lane = threadIdx.x & 31;
    int row = blockIdx.x * (blockDim.x >> 5) + warp;
    if (row >= B_ * N_) return;
    const float* xr = x + (size_t)row * D_;
    float acc[E_];
#pragma unroll
    for (int e = 0; e < E_; e++) acc[e] = 0.f;
    for (int d = lane; d < D_; d += 32) {
        float xv = xr[d];
#pragma unroll
        for (int e = 0; e < E_; e++) acc[e] += xv * sw[e * D_ + d];
    }
#pragma unroll
    for (int e = 0; e < E_; e++) {
#pragma unroll
        for (int off = 16; off; off >>= 1)
            acc[e] += __shfl_xor_sync(0xFFFFFFFFu, acc[e], off);
    }
    if (lane == 0) {
#pragma unroll
        for (int e = 0; e < E_; e++)
            g_t[(size_t)row * E_ + e] = logf(fmaxf(acc[e], 1e-6f));
    }
}

// ---------------- 2) Sinkhorn (8 iters) per batch, entirely in smem ----------------
__global__ void sinkhorn_kernel() {
    extern __shared__ float st[];                 // [E_][N_]
    __shared__ float s_m[32], s_s[32], lse_col[E_];
    int b = blockIdx.x, tid = threadIdx.x;
    for (int i = tid; i < N_ * E_; i += blockDim.x) {
        int e = i >> 12, n = i & (N_ - 1);
        st[i] = g_t[(size_t)b * N_ * E_ + (size_t)n * E_ + e];
    }
    __syncthreads();
    int warp = tid >> 5, lane = tid & 31;
    int e_w = warp & 7, seg = warp >> 3;
    for (int it = 0; it < 8; it++) {
        float m = -INFINITY, s = 0.f;
        int base = e_w * N_ + seg * 1024 + lane;
#pragma unroll 4
        for (int k = 0; k < 32; k++) {
            float v = st[base + k * 32];
            float nm = fmaxf(m, v);
            s = s * expf(m - nm) + expf(v - nm);
            m = nm;
        }
#pragma unroll
        for (int off = 16; off; off >>= 1) {
            float om = __shfl_xor_sync(0xFFFFFFFFu, m, off);
            float os = __shfl_xor_sync(0xFFFFFFFFu, s, off);
            float nm = fmaxf(m, om);
            s = s * expf(m - nm) + os * expf(om - nm);
            m = nm;
        }
        if (lane == 0) { s_m[warp] = m; s_s[warp] = s; }
        __syncthreads();
        if (tid < E_) {
            float mm = -INFINITY, ss = 0.f;
#pragma unroll
            for (int q = 0; q < 4; q++) {
                float om = s_m[q * 8 + tid], os = s_s[q * 8 + tid];
                float nm = fmaxf(mm, om);
                ss = ss * expf(mm - nm) + os * expf(om - nm);
                mm = nm;
            }
            lse_col[tid] = mm + logf(ss);
        }
        __syncthreads();
        for (int i = tid; i < N_ * E_; i += blockDim.x)
            st[i] -= lse_col[i >> 12];
        __syncthreads();
        for (int n = tid; n < N_; n += blockDim.x) {
            float mm = -INFINITY;
#pragma unroll
            for (int e = 0; e < E_; e++) mm = fmaxf(mm, st[e * N_ + n]);
            float ss = 0.f;
#pragma unroll
            for (int e = 0; e < E_; e++) ss += expf(st[e * N_ + n] - mm);
            float l = mm + logf(ss);
#pragma unroll
            for (int e = 0; e < E_; e++) st[e * N_ + n] -= l;
        }
        __syncthreads();
    }
    for (int i = tid; i < N_ * E_; i += blockDim.x)
        g_t[(size_t)b * N_ * E_ + i] = st[i];
}

// ---------------- 3) full descending sort of each (b,e) column; emit top-512 ----------------
__global__ void topk_sort_kernel() {
    __shared__ unsigned long long keys[N_];
    int b = blockIdx.x >> 3, e = blockIdx.x & 7;
    int tid = threadIdx.x;
    const float* tcol = g_t + (size_t)b * N_ * E_ + (size_t)e * N_;
    for (int i = tid; i < N_; i += blockDim.x) {
        unsigned int u = __float_as_uint(tcol[i]);
        u = (u & 0x80000000u) ? ~u : (u | 0x80000000u);
        keys[i] = ((unsigned long long)u << 32) | (unsigned int)(N_ - 1 - i);
    }
    __syncthreads();
    for (int k = 2; k <= N_; k <<= 1) {
        for (int j = k >> 1; j > 0; j >>= 1) {
            for (int i = tid; i < N_; i += blockDim.x) {
                int l = i ^ j;
                if (l > i) {
                    unsigned long long a = keys[i], c = keys[l];
                    bool desc = ((i & k) == 0);
                    if (desc ? (a < c) : (a > c)) { keys[i] = c; keys[l] = a; }
                }
            }
            __syncthreads();
        }
    }
    for (int m = tid; m < M_; m += blockDim.x) {
        unsigned long long K = keys[m];
        int n = (N_ - 1) - (int)(unsigned int)(K & 0xFFFFFFFFull);
        int o = (b * E_ + e) * M_ + m;
        g_topk_idx[o] = n;
        g_topk_val[o] = expf(tcol[n]);
    }
}

// ---------------- 4) zero output + init winner ----------------
__global__ void zero_init_kernel(float4* __restrict__ out) {
    int i = blockIdx.x * blockDim.x + threadIdx.x;
    out[i] = make_float4(0.f, 0.f, 0.f, 0.f);
    if (i < B_ * N_) g_winner[i] = -1;
}

// ---------------- 5) duplicate resolution: last-wins over (m,e) row-major ----------------
__global__ void winner_scatter_kernel() {
    int i = blockIdx.x * blockDim.x + threadIdx.x;
    if (i >= B_ * E_ * M_) return;
    int b = i / (E_ * M_);
    int r = i - b * (E_ * M_);
    int e = r / M_;
    int m = r - e * M_;
    int n = g_topk_idx[i];
    atomicMax(&g_winner[b * N_ + n], m * E_ + e);
}

// ---------------- 6) mma.sync bf16 split-precision gathered expert GEMM ----------------
// C[128,128] per CTA = gather(x)[128,1024] @ W^T[e][128 f rows,1024]
// 3 terms: Ah*Bh + Ah*Bl + Al*Bh. BK=32, double-buffered cp.async.
// smem stage: 4 tiles (Ah,Al,Bh,Bl), each 128 rows x 80B (32 bf16 + pad).
#define ROWB 80
#define TILE_B (128 * ROWB)        // 10240
#define STAGE_B (4 * TILE_B)       // 40960

// NOTE: function (not macro) — round-3 bug was macro-arg capture of loop var.
__device__ __forceinline__ void load_stage(
    uint32_t sbase, int buf, int k0, int tid,
    const __nv_bfloat16* __restrict__ xh, const __nv_bfloat16* __restrict__ xl,
    const __nv_bfloat16* __restrict__ wh, const __nv_bfloat16* __restrict__ wl,
    const int* s_n)
{
    uint32_t sb = sbase + (uint32_t)buf * STAGE_B;
#pragma unroll
    for (int i = tid; i < 2048; i += 256) {
        int t = i >> 9, r = (i >> 2) & 127, cc = i & 3;
        uint32_t dst = sb + (uint32_t)t * TILE_B + (uint32_t)r * ROWB + (uint32_t)cc * 16;
        const __nv_bfloat16* src;
        if (t == 0)      src = xh + (size_t)s_n[r] * D_ + k0 + cc * 8;
        else if (t == 1) src = xl + (size_t)s_n[r] * D_ + k0 + cc * 8;
        else if (t == 2) src = wh + (size_t)r * D_ + k0 + cc * 8;
        else             src = wl + (size_t)r * D_ + k0 + cc * 8;
        cp16(dst, src);
    }
}

__global__ __launch_bounds__(256) void expert_gemm_mma(float* __restrict__ out) {
    extern __shared__ unsigned char dynsmem[];
    __shared__ int   s_n[128];
    __shared__ float s_v[128];
    __shared__ int   s_w[128];

    int bz = blockIdx.z;  int b = bz >> 3;  int e = bz & 7;
    int m0 = blockIdx.x * 128, f0 = blockIdx.y * 128;
    int tid = threadIdx.x, wid = tid >> 5, lane = tid & 31;
    int wm = wid & 1, wn = wid >> 1;   // warp tile: rows wm*64.., cols wn*32..

    uint32_t sbase = smem_u32(dynsmem);

    if (tid < 128) {
        int o = bz * M_ + m0 + tid;
        int n = g_topk_idx[o];
        s_n[tid] = n;
        s_v[tid] = g_topk_val[o];
        s_w[tid] = (g_winner[b * N_ + n] == (m0 + tid) * E_ + e) ? 1 : 0;
    }
    __syncthreads();

    const __nv_bfloat16* xh = g_xh + (size_t)b * N_ * D_;
    const __nv_bfloat16* xl = g_xl + (size_t)b * N_ * D_;
    const __nv_bfloat16* wh = g_wth + ((size_t)e * D_ + f0) * D_;
    const __nv_bfloat16* wl = g_wtl + ((size_t)e * D_ + f0) * D_;

    float d[4][4][4];
#pragma unroll
    for (int i = 0; i < 4; i++)
#pragma unroll
        for (int j = 0; j < 4; j++)
#pragma unroll
            for (int q = 0; q < 4; q++) d[i][j][q] = 0.f;

    load_stage(sbase, 0, 0, tid, xh, xl, wh, wl, s_n);
    asm volatile("cp.async.commit_group;" ::: "memory");
    load_stage(sbase, 1, 32, tid, xh, xl, wh, wl, s_n);
    asm volatile("cp.async.commit_group;" ::: "memory");

#pragma unroll 1
    for (int c = 0; c < 32; c++) {
        if (c == 31) asm volatile("cp.async.wait_group 0;" ::: "memory");
        else         asm volatile("cp.async.wait_group 1;" ::: "memory");
        __syncthreads();

        uint32_t sb = sbase + (uint32_t)(c & 1) * STAGE_B;
#pragma unroll
        for (int kk = 0; kk < 32; kk += 16) {
            uint32_t ah[4][4], al[4][4], bh[4][2], bl[4][2];
            uint32_t acol = (uint32_t)((kk + ((lane >> 4) << 3)) * 2);
            int arow = wm * 64 + (lane & 15);
#pragma unroll
            for (int mt = 0; mt < 4; mt++) {
                uint32_t ad = sb + (uint32_t)(arow + mt * 16) * ROWB + acol;
                ldsm4(ah[mt], ad);
                ldsm4(al[mt], ad + TILE_B);
            }
            uint32_t bcol = (uint32_t)((kk + (((lane >> 3) & 1) << 3)) * 2);
            int brow0 = wn * 32 + ((lane >> 4) & 1) * 8 + (lane & 7);
#pragma unroll
            for (int p = 0; p < 2; p++) {
                uint32_t bd = sb + 2 * TILE_B + (uint32_t)(brow0 + p * 16) * ROWB + bcol;
                uint32_t t4[4];
                ldsm4(t4, bd);
                bh[2 * p][0] = t4[0]; bh[2 * p][1] = t4[1];
                bh[2 * p + 1][0] = t4[2]; bh[2 * p + 1][1] = t4[3];
                ldsm4(t4, bd + TILE_B);
                bl[2 * p][0] = t4[0]; bl[2 * p][1] = t4[1];
                bl[2 * p + 1][0] = t4[2]; bl[2 * p + 1][1] = t4[3];
            }
#pragma unroll
            for (int mt = 0; mt < 4; mt++)
#pragma unroll
                for (int nt = 0; nt < 4; nt++) mma16816(d[mt][nt], ah[mt], bh[nt]);
#pragma unroll
            for (int mt = 0; mt < 4; mt++)
#pragma unroll
                for (int nt = 0; nt < 4; nt++) mma16816(d[mt][nt], ah[mt], bl[nt]);
#pragma unroll
            for (int mt = 0; mt < 4; mt++)
#pragma unroll
                for (int nt = 0; nt < 4; nt++) mma16816(d[mt][nt], al[mt], bh[nt]);
        }
        __syncthreads();
        if (c < 30) {
            load_stage(sbase, c & 1, (c + 2) * 32, tid, xh, xl, wh, wl, s_n);
            asm volatile("cp.async.commit_group;" ::: "memory");
        }
    }

    // epilogue: scale by gate value, winner-gated scatter
#pragma unroll
    for (int mt = 0; mt < 4; mt++) {
        int rbase = wm * 64 + mt * 16 + (lane >> 2);
#pragma unroll
        for (int half = 0; half < 2; half++) {
            int r = rbase + half * 8;
            if (s_w[r]) {
                float sv = s_v[r];
                float* orow = out + ((size_t)b * N_ + s_n[r]) * D_ + f0 + wn * 32 + (lane & 3) * 2;
#pragma unroll
                for (int nt = 0; nt < 4; nt++) {
                    float2 v;
                    v.x = d[mt][nt][half * 2 + 0] * sv;
                    v.y = d[mt][nt][half * 2 + 1] * sv;
                    *(float2*)(orow + nt * 8) = v;
                }
            }
        }
    }
}

// ---------------- launch ----------------
extern "C" void kernel_launch(void* const* d_in, const int* in_sizes, int n_in,
                              void* d_out, int out_size) {
    const float* x       = (const float*)d_in[0];
    const float* gw      = (const float*)d_in[1];
    const float* experts = (const float*)d_in[2];
    float* out = (float*)d_out;

    cudaFuncSetAttribute(sinkhorn_kernel, cudaFuncAttributeMaxDynamicSharedMemorySize,
                         N_ * E_ * (int)sizeof(float));
    cudaFuncSetAttribute(expert_gemm_mma, cudaFuncAttributeMaxDynamicSharedMemorySize,
                         2 * STAGE_B);

    convert_x_kernel<<<(B_ * N_ * D_ / 4) / 256, 256>>>((const float4*)x);
    convert_w_kernel<<<dim3(32, 32, 8), dim3(32, 8)>>>(experts);
    gate_logits_kernel<<<(B_ * N_) / 8, 256>>>(x, gw);
    sinkhorn_kernel<<<B_, 1024, N_ * E_ * sizeof(float)>>>();
    topk_sort_kernel<<<B_ * E_, 1024>>>();
    zero_init_kernel<<<(B_ * N_ * D_ / 4) / 256, 256>>>((float4*)out);
    winner_scatter_kernel<<<(B_ * E_ * M_ + 255) / 256, 256>>>();
    expert_gemm_mma<<<dim3(M_ / 128, D_ / 128, B_ * E_), 256, 2 * STAGE_B>>>(out);
}

// round 5
// speedup vs baseline: 2.7530x; 1.2263x over previous
#include <cuda_runtime.h>
#include <cuda_bf16.h>
#include <math.h>
#include <stdint.h>

#define B_ 4
#define N_ 4096
#define D_ 1024
#define E_ 8
#define M_ 512   // N/E tokens per expert

// ---------------- scratch (device globals; no allocation allowed) ----------------
__device__ float g_t[B_ * N_ * E_];         // gate logits -> log-gates; after sinkhorn: [b][e][n] layout
__device__ int   g_topk_idx[B_ * E_ * M_];  // sorted token indices per (b,e), descending gate
__device__ float g_topk_val[B_ * E_ * M_];  // matching gate values
__device__ int   g_winner[B_ * N_];         // per-token winning key m*E+e (last-wins), -1 if unrouted

// tf32 (RNA-rounded) operands for the tensor-core GEMM
__device__ float g_xt[B_ * N_ * D_];   // tf32(x)
__device__ float g_wt[E_ * D_ * D_];   // tf32(W^T): [e][f][k]

__device__ __forceinline__ uint32_t smem_u32(const void* p) {
    uint32_t a;
    asm("{ .reg .u64 t; cvta.to.shared.u64 t, %1; cvt.u32.u64 %0, t; }" : "=r"(a) : "l"(p));
    return a;
}
__device__ __forceinline__ void cp16(uint32_t dst, const void* src) {
    asm volatile("cp.async.cg.shared.global [%0], [%1], 16;" :: "r"(dst), "l"(src));
}
__device__ __forceinline__ uint32_t f2tf32(float f) {
    uint32_t u;
    asm("cvt.rna.tf32.f32 %0, %1;" : "=r"(u) : "f"(f));
    return u;
}
__device__ __forceinline__ void mma_tf32(float* d, const uint32_t* a, const uint32_t* b) {
    asm volatile(
        "mma.sync.aligned.m16n8k8.row.col.f32.tf32.tf32.f32 "
        "{%0,%1,%2,%3}, {%4,%5,%6,%7}, {%8,%9}, {%0,%1,%2,%3};"
        : "+f"(d[0]), "+f"(d[1]), "+f"(d[2]), "+f"(d[3])
        : "r"(a[0]), "r"(a[1]), "r"(a[2]), "r"(a[3]), "r"(b[0]), "r"(b[1]));
}

// ---------------- 0a) x -> tf32 (RNA) ----------------
__global__ void convert_x_kernel(const float4* __restrict__ x) {
    int i = blockIdx.x * blockDim.x + threadIdx.x;  // over B*N*D/4
    float4 v = x[i];
    uint4 o;
    o.x = f2tf32(v.x); o.y = f2tf32(v.y); o.z = f2tf32(v.z); o.w = f2tf32(v.w);
    ((uint4*)g_xt)[i] = o;
}

// ---------------- 0b) experts -> transposed [e][f][k] tf32 (RNA) ----------------
__global__ void convert_w_kernel(const float* __restrict__ w) {
    __shared__ float t[32][33];
    int e = blockIdx.z;
    int k0 = blockIdx.x * 32, f0 = blockIdx.y * 32;
    int tx = threadIdx.x, ty = threadIdx.y;  // 32 x 8
    const float* wb = w + (size_t)e * D_ * D_;
#pragma unroll
    for (int j = 0; j < 32; j += 8)
        t[ty + j][tx] = wb[(size_t)(k0 + ty + j) * D_ + f0 + tx];
    __syncthreads();
#pragma unroll
    for (int j = 0; j < 32; j += 8) {
        size_t o = (size_t)e * D_ * D_ + (size_t)(f0 + ty + j) * D_ + k0 + tx;
        ((uint32_t*)g_wt)[o] = f2tf32(t[tx][ty + j]);
    }
}

// ---------------- 1) gate logits + log(clamp(.,1e-6)) ----------------
__global__ void gate_logits_kernel(const float* __restrict__ x, const float* __restrict__ gw) {
    __shared__ float sw[E_ * D_];  // transposed: [e][d]
    for (int i = threadIdx.x; i < D_ * E_; i += blockDim.x) {
        int d = i / E_, e = i % E_;
        sw[e * D_ + d] = gw[i];
    }
    __syncthreads();
    int warp = threadIdx.x >> 5, lane = threadIdx.x & 31;
    int row = blockIdx.x * (blockDim.x >> 5) + warp;
    if (row >= B_ * N_) return;
    const float* xr = x + (size_t)row * D_;
    float acc[E_];
#pragma unroll
    for (int e = 0; e < E_; e++) acc[e] = 0.f;
    for (int d = lane; d < D_; d += 32) {
        float xv = xr[d];
#pragma unroll
        for (int e = 0; e < E_; e++) acc[e] += xv * sw[e * D_ + d];
    }
#pragma unroll
    for (int e = 0; e < E_; e++) {
#pragma unroll
        for (int off = 16; off; off >>= 1)
            acc[e] += __shfl_xor_sync(0xFFFFFFFFu, acc[e], off);
    }
    if (lane == 0) {
#pragma unroll
        for (int e = 0; e < E_; e++)
            g_t[(size_t)row * E_ + e] = logf(fmaxf(acc[e], 1e-6f));
    }
}

// ---------------- 2) Sinkhorn (8 iters) per batch; two-pass LSE + fast-math ----------------
__global__ void sinkhorn_kernel() {
    extern __shared__ float st[];                 // [E_][N_]
    __shared__ float s_m[32], s_s[32], lse_col[E_];
    int b = blockIdx.x, tid = threadIdx.x;
    for (int i = tid; i < N_ * E_; i += blockDim.x) {
        int e = i >> 12, n = i & (N_ - 1);
        st[i] = g_t[(size_t)b * N_ * E_ + (size_t)n * E_ + e];
    }
    __syncthreads();
    int warp = tid >> 5, lane = tid & 31;
    int e_w = warp & 7, seg = warp >> 3;
    for (int it = 0; it < 8; it++) {
        // ---- column LSE (over tokens), two-pass ----
        int base = e_w * N_ + seg * 1024 + lane;
        float m = -INFINITY;
#pragma unroll 8
        for (int k = 0; k < 32; k++) m = fmaxf(m, st[base + k * 32]);
#pragma unroll
        for (int off = 16; off; off >>= 1)
            m = fmaxf(m, __shfl_xor_sync(0xFFFFFFFFu, m, off));
        float s = 0.f;
#pragma unroll 8
        for (int k = 0; k < 32; k++) s += __expf(st[base + k * 32] - m);
#pragma unroll
        for (int off = 16; off; off >>= 1)
            s += __shfl_xor_sync(0xFFFFFFFFu, s, off);
        if (lane == 0) { s_m[warp] = m; s_s[warp] = s; }
        __syncthreads();
        if (tid < E_) {
            float mm = fmaxf(fmaxf(s_m[tid], s_m[8 + tid]), fmaxf(s_m[16 + tid], s_m[24 + tid]));
            float ss = 0.f;
#pragma unroll
            for (int q = 0; q < 4; q++) ss += s_s[q * 8 + tid] * __expf(s_m[q * 8 + tid] - mm);
            lse_col[tid] = mm + __logf(ss);
        }
        __syncthreads();
        for (int i = tid; i < N_ * E_; i += blockDim.x)
            st[i] -= lse_col[i >> 12];
        __syncthreads();
        // ---- row LSE (over experts), per-thread two-pass ----
        for (int n = tid; n < N_; n += blockDim.x) {
            float mm = -INFINITY;
#pragma unroll
            for (int e = 0; e < E_; e++) mm = fmaxf(mm, st[e * N_ + n]);
            float ss = 0.f;
#pragma unroll
            for (int e = 0; e < E_; e++) ss += __expf(st[e * N_ + n] - mm);
            float l = mm + __logf(ss);
#pragma unroll
            for (int e = 0; e < E_; e++) st[e * N_ + n] -= l;
        }
        __syncthreads();
    }
    for (int i = tid; i < N_ * E_; i += blockDim.x)
        g_t[(size_t)b * N_ * E_ + i] = st[i];
}

// ---------------- 3) full descending sort of each (b,e) column; emit top-512 ----------------
__global__ void topk_sort_kernel() {
    __shared__ unsigned long long keys[N_];
    int b = blockIdx.x >> 3, e = blockIdx.x & 7;
    int tid = threadIdx.x;
    const float* tcol = g_t + (size_t)b * N_ * E_ + (size_t)e * N_;
    for (int i = tid; i < N_; i += blockDim.x) {
        unsigned int u = __float_as_uint(tcol[i]);
        u = (u & 0x80000000u) ? ~u : (u | 0x80000000u);
        keys[i] = ((unsigned long long)u << 32) | (unsigned int)(N_ - 1 - i);
    }
    __syncthreads();
    for (int k = 2; k <= N_; k <<= 1) {
        for (int j = k >> 1; j > 0; j >>= 1) {
            for (int i = tid; i < N_; i += blockDim.x) {
                int l = i ^ j;
                if (l > i) {
                    unsigned long long a = keys[i], c = keys[l];
                    bool desc = ((i & k) == 0);
                    if (desc ? (a < c) : (a > c)) { keys[i] = c; keys[l] = a; }
                }
            }
            __syncthreads();
        }
    }
    for (int m = tid; m < M_; m += blockDim.x) {
        unsigned long long K = keys[m];
        int n = (N_ - 1) - (int)(unsigned int)(K & 0xFFFFFFFFull);
        int o = (b * E_ + e) * M_ + m;
        g_topk_idx[o] = n;
        g_topk_val[o] = expf(tcol[n]);
    }
}

// ---------------- 4) init winner ----------------
__global__ void winner_init_kernel() {
    int i = blockIdx.x * blockDim.x + threadIdx.x;
    if (i < B_ * N_) g_winner[i] = -1;
}

// ---------------- 5) duplicate resolution: last-wins over (m,e) row-major ----------------
__global__ void winner_scatter_kernel() {
    int i = blockIdx.x * blockDim.x + threadIdx.x;
    if (i >= B_ * E_ * M_) return;
    int b = i / (E_ * M_);
    int r = i - b * (E_ * M_);
    int e = r / M_;
    int m = r - e * M_;
    int n = g_topk_idx[i];
    atomicMax(&g_winner[b * N_ + n], m * E_ + e);
}

// ---------------- 5b) zero only unrouted rows ----------------
__global__ void zero_unrouted_kernel(float4* __restrict__ out) {
    int row = blockIdx.x;                 // b*N + n
    if (g_winner[row] >= 0) return;
    float4 z = make_float4(0.f, 0.f, 0.f, 0.f);
    out[(size_t)row * (D_ / 4) + threadIdx.x] = z;
}

// ---------------- 6) tf32 mma.sync gathered expert GEMM ----------------
// C[128,128] per CTA = tf32(gather(x))[128,1024] @ tf32(W^T)[128 f rows,1024]
// BK=32, double-buffered cp.async; smem rows padded to 36 floats (conflict-free).
#define ROWF 36
#define TILE_F (128 * ROWF * 4)        // 18432 bytes per operand tile
#define STAGE_F (2 * TILE_F)           // 36864

__device__ __forceinline__ void load_stage_t(
    uint32_t sbase, int buf, int k0, int tid,
    const float* __restrict__ xt, const float* __restrict__ wt, const int* s_n)
{
    uint32_t sb = sbase + (uint32_t)buf * STAGE_F;
#pragma unroll
    for (int i = tid; i < 2048; i += 256) {
        int t = i >> 10, r = (i >> 3) & 127, cc = i & 7;
        uint32_t dst = sb + (uint32_t)t * TILE_F + (uint32_t)r * (ROWF * 4) + (uint32_t)cc * 16;
        const float* src = (t == 0) ? xt + (size_t)s_n[r] * D_ + k0 + cc * 4
                                    : wt + (size_t)r * D_ + k0 + cc * 4;
        cp16(dst, src);
    }
}

__global__ __launch_bounds__(256) void expert_gemm_mma(float* __restrict__ out) {
    extern __shared__ unsigned char dynsmem[];
    __shared__ int   s_n[128];
    __shared__ float s_v[128];
    __shared__ int   s_w[128];

    int bz = blockIdx.z;  int b = bz >> 3;  int e = bz & 7;
    int m0 = blockIdx.x * 128, f0 = blockIdx.y * 128;
    int tid = threadIdx.x, wid = tid >> 5, lane = tid & 31;
    int wm = wid & 1, wn = wid >> 1;   // warp tile: rows wm*64.., cols wn*32..

    uint32_t sbase = smem_u32(dynsmem);
    const uint32_t* smw = (const uint32_t*)dynsmem;

    if (tid < 128) {
        int o = bz * M_ + m0 + tid;
        int n = g_topk_idx[o];
        s_n[tid] = n;
        s_v[tid] = g_topk_val[o];
        s_w[tid] = (g_winner[b * N_ + n] == (m0 + tid) * E_ + e) ? 1 : 0;
    }
    __syncthreads();

    const float* xt = g_xt + (size_t)b * N_ * D_;
    const float* wt = g_wt + ((size_t)e * D_ + f0) * D_;

    float d[4][4][4];
#pragma unroll
    for (int i = 0; i < 4; i++)
#pragma unroll
        for (int j = 0; j < 4; j++)
#pragma unroll
            for (int q = 0; q < 4; q++) d[i][j][q] = 0.f;

    load_stage_t(sbase, 0, 0, tid, xt, wt, s_n);
    asm volatile("cp.async.commit_group;" ::: "memory");
    load_stage_t(sbase, 1, 32, tid, xt, wt, s_n);
    asm volatile("cp.async.commit_group;" ::: "memory");

    int qa = lane >> 2, ma = lane & 3;   // groupID, thread-in-group

#pragma unroll 1
    for (int c = 0; c < 32; c++) {
        if (c == 31) asm volatile("cp.async.wait_group 0;" ::: "memory");
        else         asm volatile("cp.async.wait_group 1;" ::: "memory");
        __syncthreads();

        const uint32_t* sbA = smw + (size_t)(c & 1) * (STAGE_F / 4);
        const uint32_t* sbB = sbA + TILE_F / 4;
#pragma unroll
        for (int kk = 0; kk < 32; kk += 8) {
            uint32_t afr[4][4], bfr[4][2];
#pragma unroll
            for (int mt = 0; mt < 4; mt++) {
                int r0 = wm * 64 + mt * 16 + qa;
                afr[mt][0] = sbA[r0 * ROWF + kk + ma];
                afr[mt][1] = sbA[(r0 + 8) * ROWF + kk + ma];
                afr[mt][2] = sbA[r0 * ROWF + kk + ma + 4];
                afr[mt][3] = sbA[(r0 + 8) * ROWF + kk + ma + 4];
            }
#pragma unroll
            for (int nt = 0; nt < 4; nt++) {
                int fc = wn * 32 + nt * 8 + qa;
                bfr[nt][0] = sbB[fc * ROWF + kk + ma];
                bfr[nt][1] = sbB[fc * ROWF + kk + ma + 4];
            }
#pragma unroll
            for (int mt = 0; mt < 4; mt++)
#pragma unroll
                for (int nt = 0; nt < 4; nt++) mma_tf32(d[mt][nt], afr[mt], bfr[nt]);
        }
        __syncthreads();
        if (c < 30) {
            load_stage_t(sbase, c & 1, (c + 2) * 32, tid, xt, wt, s_n);
            asm volatile("cp.async.commit_group;" ::: "memory");
        }
    }

    // epilogue: scale by gate value, winner-gated scatter
#pragma unroll
    for (int mt = 0; mt < 4; mt++) {
        int rbase = wm * 64 + mt * 16 + qa;
#pragma unroll
        for (int half = 0; half < 2; half++) {
            int r = rbase + half * 8;
            if (s_w[r]) {
                float sv = s_v[r];
                float* orow = out + ((size_t)b * N_ + s_n[r]) * D_ + f0 + wn * 32 + ma * 2;
#pragma unroll
                for (int nt = 0; nt < 4; nt++) {
                    float2 v;
                    v.x = d[mt][nt][half * 2 + 0] * sv;
                    v.y = d[mt][nt][half * 2 + 1] * sv;
                    *(float2*)(orow + nt * 8) = v;
                }
            }
        }
    }
}

// ---------------- launch ----------------
extern "C" void kernel_launch(void* const* d_in, const int* in_sizes, int n_in,
                              void* d_out, int out_size) {
    const float* x       = (const float*)d_in[0];
    const float* gw      = (const float*)d_in[1];
    const float* experts = (const float*)d_in[2];
    float* out = (float*)d_out;

    cudaFuncSetAttribute(sinkhorn_kernel, cudaFuncAttributeMaxDynamicSharedMemorySize,
                         N_ * E_ * (int)sizeof(float));
    cudaFuncSetAttribute(expert_gemm_mma, cudaFuncAttributeMaxDynamicSharedMemorySize,
                         2 * STAGE_F);

    convert_x_kernel<<<(B_ * N_ * D_ / 4) / 256, 256>>>((const float4*)x);
    convert_w_kernel<<<dim3(32, 32, 8), dim3(32, 8)>>>(experts);
    gate_logits_kernel<<<(B_ * N_) / 8, 256>>>(x, gw);
    sinkhorn_kernel<<<B_, 1024, N_ * E_ * sizeof(float)>>>();
    topk_sort_kernel<<<B_ * E_, 1024>>>();
    winner_init_kernel<<<(B_ * N_) / 256, 256>>>();
    winner_scatter_kernel<<<(B_ * E_ * M_ + 255) / 256, 256>>>();
    zero_unrouted_kernel<<<B_ * N_, 256>>>((float4*)out);
    expert_gemm_mma<<<dim3(M_ / 128, D_ / 128, B_ * E_), 256, 2 * STAGE_F>>>(out);
}

// round 6
// speedup vs baseline: 2.9880x; 1.0854x over previous
#include <cuda_runtime.h>
#include <cuda_bf16.h>
#include <math.h>
#include <stdint.h>

#define B_ 4
#define N_ 4096
#define D_ 1024
#define E_ 8
#define M_ 512   // N/E tokens per expert

// ---------------- scratch (device globals; no allocation allowed) ----------------
__device__ float g_t[B_ * N_ * E_];         // log(clamp(gate logits)) [b][n][e], read-only after k1
__device__ float g_r[B_ * N_];              // sinkhorn row (token) offsets
__device__ float g_c[B_ * E_];              // sinkhorn col (expert) offsets
__device__ int   g_topk_idx[B_ * E_ * M_];  // sorted token indices per (b,e), descending gate
__device__ float g_topk_val[B_ * E_ * M_];  // matching gate values
__device__ int   g_winner[B_ * N_];         // per-token winning key m*E+e (last-wins), -1 if unrouted

// tf32 (RNA-rounded) operands for the tensor-core GEMM
__device__ float g_xt[B_ * N_ * D_];   // tf32(x)
__device__ float g_wt[E_ * D_ * D_];   // tf32(W^T): [e][f][k]

__device__ __forceinline__ uint32_t smem_u32(const void* p) {
    uint32_t a;
    asm("{ .reg .u64 t; cvta.to.shared.u64 t, %1; cvt.u32.u64 %0, t; }" : "=r"(a) : "l"(p));
    return a;
}
__device__ __forceinline__ void cp16(uint32_t dst, const void* src) {
    asm volatile("cp.async.cg.shared.global [%0], [%1], 16;" :: "r"(dst), "l"(src));
}
__device__ __forceinline__ uint32_t f2tf32(float f) {
    uint32_t u;
    asm("cvt.rna.tf32.f32 %0, %1;" : "=r"(u) : "f"(f));
    return u;
}
__device__ __forceinline__ void mma_tf32(float* d, const uint32_t* a, const uint32_t* b) {
    asm volatile(
        "mma.sync.aligned.m16n8k8.row.col.f32.tf32.tf32.f32 "
        "{%0,%1,%2,%3}, {%4,%5,%6,%7}, {%8,%9}, {%0,%1,%2,%3};"
        : "+f"(d[0]), "+f"(d[1]), "+f"(d[2]), "+f"(d[3])
        : "r"(a[0]), "r"(a[1]), "r"(a[2]), "r"(a[3]), "r"(b[0]), "r"(b[1]));
}

// ========== k1: gate logits (+log clamp) + convert x->tf32 + convert W->W^T tf32 + winner init ==========
__global__ __launch_bounds__(256) void gate_fused_kernel(
    const float* __restrict__ x, const float* __restrict__ gw, const float* __restrict__ w) {
    __shared__ float sw[E_ * D_];   // gate weights transposed [e][d]
    __shared__ float wt[32][33];    // W transpose tile

    int tid = threadIdx.x;
    for (int i = tid; i < D_ * E_; i += 256) {
        int d = i / E_, e = i % E_;
        sw[e * D_ + d] = gw[i];
    }
    if (blockIdx.x < (B_ * N_) / 256)
        g_winner[blockIdx.x * 256 + tid] = -1;
    __syncthreads();

    // gate logits + x conversion: 8 warps, one token row each
    int warp = tid >> 5, lane = tid & 31;
    int row = blockIdx.x * 8 + warp;
    {
        const float* xr = x + (size_t)row * D_;
        uint32_t* xo = (uint32_t*)(g_xt + (size_t)row * D_);
        float acc[E_];
#pragma unroll
        for (int e = 0; e < E_; e++) acc[e] = 0.f;
        for (int d = lane; d < D_; d += 32) {
            float xv = xr[d];
            xo[d] = f2tf32(xv);
#pragma unroll
            for (int e = 0; e < E_; e++) acc[e] += xv * sw[e * D_ + d];
        }
#pragma unroll
        for (int e = 0; e < E_; e++) {
#pragma unroll
            for (int off = 16; off; off >>= 1)
                acc[e] += __shfl_xor_sync(0xFFFFFFFFu, acc[e], off);
        }
        if (lane == 0) {
#pragma unroll
            for (int e = 0; e < E_; e++)
                g_t[(size_t)row * E_ + e] = logf(fmaxf(acc[e], 1e-6f));
        }
    }

    // W transpose + tf32: 4 tiles of 32x32 per block (8192 tiles total)
    int tx = tid & 31, tyy = tid >> 5;  // 32 x 8
#pragma unroll 1
    for (int t = 0; t < 4; t++) {
        int tile = blockIdx.x * 4 + t;
        int e = tile >> 10;
        int rem = tile & 1023;
        int k0 = (rem >> 5) * 32, f0 = (rem & 31) * 32;
        const float* wb = w + (size_t)e * D_ * D_;
        __syncthreads();
#pragma unroll
        for (int j = 0; j < 32; j += 8)
            wt[tyy + j][tx] = wb[(size_t)(k0 + tyy + j) * D_ + f0 + tx];
        __syncthreads();
#pragma unroll
        for (int j = 0; j < 32; j += 8) {
            size_t o = (size_t)e * D_ * D_ + (size_t)(f0 + tyy + j) * D_ + k0 + tx;
            ((uint32_t*)g_wt)[o] = f2tf32(wt[tx][tyy + j]);
        }
    }
}

// ========== k2: Sinkhorn u/v form: c_e = LSE_n(t0 - r), r_n = LSE_e(t0 - c) ==========
#define SROW 4100   // padded row pitch (floats) -> conflict-free both phases
__global__ __launch_bounds__(1024) void sinkhorn_kernel() {
    extern __shared__ float sm[];          // st[8][SROW] then sr[4096]
    float* st = sm;
    float* sr = sm + 8 * SROW;
    __shared__ float s_pm[32], s_ps[32], s_c[E_];

    int b = blockIdx.x, tid = threadIdx.x;
    // load t0 transposed into [e][n] (coalesced gmem read, conflict-free smem write via pitch)
    const float* tb = g_t + (size_t)b * N_ * E_;
    for (int i = tid; i < N_ * E_; i += 1024) {
        int n = i >> 3, e = i & 7;
        st[e * SROW + n] = tb[i];
    }
    for (int n = tid; n < N_; n += 1024) sr[n] = 0.f;
    __syncthreads();

    int warp = tid >> 5, lane = tid & 31;
    int e_w = warp & 7, seg = warp >> 3;   // 4 warps per expert, 1024-token segments

    for (int it = 0; it < 8; it++) {
        // ---- col phase: c_e = LSE_n(st[e][n] - sr[n]) ----
        int base = seg * 1024 + lane;
        const float* se = st + e_w * SROW;
        float m = -INFINITY;
#pragma unroll 8
        for (int k = 0; k < 32; k++) m = fmaxf(m, se[base + k * 32] - sr[base + k * 32]);
#pragma unroll
        for (int off = 16; off; off >>= 1)
            m = fmaxf(m, __shfl_xor_sync(0xFFFFFFFFu, m, off));
        float s = 0.f;
#pragma unroll 8
        for (int k = 0; k < 32; k++) s += __expf(se[base + k * 32] - sr[base + k * 32] - m);
#pragma unroll
        for (int off = 16; off; off >>= 1)
            s += __shfl_xor_sync(0xFFFFFFFFu, s, off);
        if (lane == 0) { s_pm[warp] = m; s_ps[warp] = s; }
        __syncthreads();
        if (tid < E_) {
            float mm = fmaxf(fmaxf(s_pm[tid], s_pm[8 + tid]), fmaxf(s_pm[16 + tid], s_pm[24 + tid]));
            float ss = 0.f;
#pragma unroll
            for (int q = 0; q < 4; q++) ss += s_ps[q * 8 + tid] * __expf(s_pm[q * 8 + tid] - mm);
            s_c[tid] = mm + __logf(ss);
        }
        __syncthreads();
        // ---- row phase: sr[n] = LSE_e(st[e][n] - c_e) ----
        float c0 = s_c[0], c1 = s_c[1], c2 = s_c[2], c3 = s_c[3];
        float c4 = s_c[4], c5 = s_c[5], c6 = s_c[6], c7 = s_c[7];
#pragma unroll
        for (int q = 0; q < 4; q++) {
            int n = tid + q * 1024;
            float v0 = st[0 * SROW + n] - c0, v1 = st[1 * SROW + n] - c1;
            float v2 = st[2 * SROW + n] - c2, v3 = st[3 * SROW + n] - c3;
            float v4 = st[4 * SROW + n] - c4, v5 = st[5 * SROW + n] - c5;
            float v6 = st[6 * SROW + n] - c6, v7 = st[7 * SROW + n] - c7;
            float mm = fmaxf(fmaxf(fmaxf(v0, v1), fmaxf(v2, v3)),
                             fmaxf(fmaxf(v4, v5), fmaxf(v6, v7)));
            float ss = __expf(v0 - mm) + __expf(v1 - mm) + __expf(v2 - mm) + __expf(v3 - mm)
                     + __expf(v4 - mm) + __expf(v5 - mm) + __expf(v6 - mm) + __expf(v7 - mm);
            sr[n] = mm + __logf(ss);
        }
        __syncthreads();
    }
    for (int n = tid; n < N_; n += 1024) g_r[b * N_ + n] = sr[n];
    if (tid < E_) g_c[b * E_ + tid] = s_c[tid];
}

// ========== k3: top-512 sort per (b,e) + winner scatter ==========
__global__ __launch_bounds__(1024) void topk_winner_kernel() {
    __shared__ unsigned long long keys[N_];
    int b = blockIdx.x >> 3, e = blockIdx.x & 7;
    int tid = threadIdx.x;
    const float* tb = g_t + (size_t)b * N_ * E_ + e;   // stride E_
    const float* rb = g_r + (size_t)b * N_;
    float ce = g_c[b * E_ + e];

    for (int i = tid; i < N_; i += 1024) {
        float v = tb[(size_t)i * E_] - rb[i];          // per-column ordering invariant to -ce shift
        unsigned int u = __float_as_uint(v);
        u = (u & 0x80000000u) ? ~u : (u | 0x80000000u);
        keys[i] = ((unsigned long long)u << 32) | (unsigned int)(N_ - 1 - i);
    }
    __syncthreads();
    for (int k = 2; k <= N_; k <<= 1) {
        for (int j = k >> 1; j > 0; j >>= 1) {
            for (int i = tid; i < N_; i += 1024) {
                int l = i ^ j;
                if (l > i) {
                    unsigned long long a = keys[i], c = keys[l];
                    bool desc = ((i & k) == 0);
                    if (desc ? (a < c) : (a > c)) { keys[i] = c; keys[l] = a; }
                }
            }
            __syncthreads();
        }
    }
    for (int m = tid; m < M_; m += 1024) {
        unsigned long long K = keys[m];
        int n = (N_ - 1) - (int)(unsigned int)(K & 0xFFFFFFFFull);
        int o = (b * E_ + e) * M_ + m;
        g_topk_idx[o] = n;
        g_topk_val[o] = expf(tb[(size_t)n * E_] - rb[n] - ce);
        atomicMax(&g_winner[b * N_ + n], m * E_ + e);   // last-wins over row-major (m,e)
    }
}

// ========== k4: tf32 mma.sync gathered expert GEMM (PROFILED LAUNCH) ==========
#define ROWF 36
#define TILE_F (128 * ROWF * 4)        // 18432 bytes per operand tile
#define STAGE_F (2 * TILE_F)           // 36864

__device__ __forceinline__ void load_stage_t(
    uint32_t sbase, int buf, int k0, int tid,
    const float* __restrict__ xt, const float* __restrict__ wt, const int* s_n)
{
    uint32_t sb = sbase + (uint32_t)buf * STAGE_F;
#pragma unroll
    for (int i = tid; i < 2048; i += 256) {
        int t = i >> 10, r = (i >> 3) & 127, cc = i & 7;
        uint32_t dst = sb + (uint32_t)t * TILE_F + (uint32_t)r * (ROWF * 4) + (uint32_t)cc * 16;
        const float* src = (t == 0) ? xt + (size_t)s_n[r] * D_ + k0 + cc * 4
                                    : wt + (size_t)r * D_ + k0 + cc * 4;
        cp16(dst, src);
    }
}

__global__ __launch_bounds__(256) void expert_gemm_mma(float* __restrict__ out) {
    extern __shared__ unsigned char dynsmem[];
    __shared__ int   s_n[128];
    __shared__ float s_v[128];
    __shared__ int   s_w[128];

    int bz = blockIdx.z;  int b = bz >> 3;  int e = bz & 7;
    int m0 = blockIdx.x * 128, f0 = blockIdx.y * 128;
    int tid = threadIdx.x, wid = tid >> 5, lane = tid & 31;
    int wm = wid & 1, wn = wid >> 1;

    uint32_t sbase = smem_u32(dynsmem);
    const uint32_t* smw = (const uint32_t*)dynsmem;

    if (tid < 128) {
        int o = bz * M_ + m0 + tid;
        int n = g_topk_idx[o];
        s_n[tid] = n;
        s_v[tid] = g_topk_val[o];
        s_w[tid] = (g_winner[b * N_ + n] == (m0 + tid) * E_ + e) ? 1 : 0;
    }
    __syncthreads();

    const float* xt = g_xt + (size_t)b * N_ * D_;
    const float* wt = g_wt + ((size_t)e * D_ + f0) * D_;

    float d[4][4][4];
#pragma unroll
    for (int i = 0; i < 4; i++)
#pragma unroll
        for (int j = 0; j < 4; j++)
#pragma unroll
            for (int q = 0; q < 4; q++) d[i][j][q] = 0.f;

    load_stage_t(sbase, 0, 0, tid, xt, wt, s_n);
    asm volatile("cp.async.commit_group;" ::: "memory");
    load_stage_t(sbase, 1, 32, tid, xt, wt, s_n);
    asm volatile("cp.async.commit_group;" ::: "memory");

    int qa = lane >> 2, ma = lane & 3;

#pragma unroll 1
    for (int c = 0; c < 32; c++) {
        if (c == 31) asm volatile("cp.async.wait_group 0;" ::: "memory");
        else         asm volatile("cp.async.wait_group 1;" ::: "memory");
        __syncthreads();

        const uint32_t* sbA = smw + (size_t)(c & 1) * (STAGE_F / 4);
        const uint32_t* sbB = sbA + TILE_F / 4;
#pragma unroll
        for (int kk = 0; kk < 32; kk += 8) {
            uint32_t afr[4][4], bfr[4][2];
#pragma unroll
            for (int mt = 0; mt < 4; mt++) {
                int r0 = wm * 64 + mt * 16 + qa;
                afr[mt][0] = sbA[r0 * ROWF + kk + ma];
                afr[mt][1] = sbA[(r0 + 8) * ROWF + kk + ma];
                afr[mt][2] = sbA[r0 * ROWF + kk + ma + 4];
                afr[mt][3] = sbA[(r0 + 8) * ROWF + kk + ma + 4];
            }
#pragma unroll
            for (int nt = 0; nt < 4; nt++) {
                int fc = wn * 32 + nt * 8 + qa;
                bfr[nt][0] = sbB[fc * ROWF + kk + ma];
                bfr[nt][1] = sbB[fc * ROWF + kk + ma + 4];
            }
#pragma unroll
            for (int mt = 0; mt < 4; mt++)
#pragma unroll
                for (int nt = 0; nt < 4; nt++) mma_tf32(d[mt][nt], afr[mt], bfr[nt]);
        }
        __syncthreads();
        if (c < 30) {
            load_stage_t(sbase, c & 1, (c + 2) * 32, tid, xt, wt, s_n);
            asm volatile("cp.async.commit_group;" ::: "memory");
        }
    }

#pragma unroll
    for (int mt = 0; mt < 4; mt++) {
        int rbase = wm * 64 + mt * 16 + qa;
#pragma unroll
        for (int half = 0; half < 2; half++) {
            int r = rbase + half * 8;
            if (s_w[r]) {
                float sv = s_v[r];
                float* orow = out + ((size_t)b * N_ + s_n[r]) * D_ + f0 + wn * 32 + ma * 2;
#pragma unroll
                for (int nt = 0; nt < 4; nt++) {
                    float2 v;
                    v.x = d[mt][nt][half * 2 + 0] * sv;
                    v.y = d[mt][nt][half * 2 + 1] * sv;
                    *(float2*)(orow + nt * 8) = v;
                }
            }
        }
    }
}

// ========== k5: zero only unrouted rows (disjoint from GEMM-written rows) ==========
__global__ void zero_unrouted_kernel(float4* __restrict__ out) {
    int row = blockIdx.x;                 // b*N + n
    if (g_winner[row] >= 0) return;
    out[(size_t)row * (D_ / 4) + threadIdx.x] = make_float4(0.f, 0.f, 0.f, 0.f);
}

// ---------------- launch ----------------
extern "C" void kernel_launch(void* const* d_in, const int* in_sizes, int n_in,
                              void* d_out, int out_size) {
    const float* x       = (const float*)d_in[0];
    const float* gw      = (const float*)d_in[1];
    const float* experts = (const float*)d_in[2];
    float* out = (float*)d_out;

    cudaFuncSetAttribute(sinkhorn_kernel, cudaFuncAttributeMaxDynamicSharedMemorySize,
                         (8 * SROW + N_) * (int)sizeof(float));
    cudaFuncSetAttribute(expert_gemm_mma, cudaFuncAttributeMaxDynamicSharedMemorySize,
                         2 * STAGE_F);

    gate_fused_kernel<<<(B_ * N_) / 8, 256>>>(x, gw, experts);
    sinkhorn_kernel<<<B_, 1024, (8 * SROW + N_) * sizeof(float)>>>();
    topk_winner_kernel<<<B_ * E_, 1024>>>();
    expert_gemm_mma<<<dim3(M_ / 128, D_ / 128, B_ * E_), 256, 2 * STAGE_F>>>(out);
    zero_unrouted_kernel<<<B_ * N_, 256>>>((float4*)out);
}